// round 16
// baseline (speedup 1.0000x reference)
#include <cuda_runtime.h>
#include <math.h>

#define B 16
#define LQ 2048
#define EMB1 1024
#define EMB2 768
#define HDIM 1024
#define NHEAD 16
#define DH 64
#define GRIDX 18      // main grid (18,16) = 288 blocks = 144 SMs x 2

// Scratch (static device globals; no allocation in kernel_launch).
__device__ float g_K[B * HDIM];
__device__ float g_V[B * HDIM];
__device__ float g_Weff[B * NHEAD * EMB1];
__device__ float g_c[B * NHEAD];

// Packed f32x2 FMA: acc = a*b + acc elementwise on (lo,hi) float pairs.
__device__ __forceinline__ void fma2(unsigned long long& acc,
                                     unsigned long long a, unsigned long long b) {
    asm("fma.rn.f32x2 %0, %1, %2, %0;" : "+l"(acc) : "l"(a), "l"(b));
}
__device__ __forceinline__ float unpack_sum(unsigned long long a) {
    float lo, hi;
    asm("mov.b64 {%0, %1}, %2;" : "=f"(lo), "=f"(hi) : "l"(a));
    return lo + hi;
}

// ---------------------------------------------------------------------------
// Kernel 1 (exact R15, proven): 512 blocks x 256 thr, block stages 2
// j-columns of both Wk and Wv (12 KB); warp w handles batches {w, w+8}.
// ---------------------------------------------------------------------------
__global__ __launch_bounds__(256, 4) void kv_kernel(const float* __restrict__ emb2,
                          const float* __restrict__ Wk, const float* __restrict__ bk,
                          const float* __restrict__ Wv, const float* __restrict__ bv) {
    __shared__ float4 ws[768];     // [0:192) Wk j0 | [192:384) Wk j1
                                   // [384:576) Wv j0 | [576:768) Wv j1
    int j0 = blockIdx.x * 2;
    int tid = threadIdx.x;

    const float4* Wk4 = (const float4*)(Wk + j0 * EMB2);
    const float4* Wv4 = (const float4*)(Wv + j0 * EMB2);
    for (int t = tid; t < 384; t += 256) ws[t] = __ldg(Wk4 + t);
    for (int t = tid; t < 384; t += 256) ws[384 + t] = __ldg(Wv4 + t);
    __syncthreads();

    int w = tid >> 5, lane = tid & 31;

#pragma unroll
    for (int bb = 0; bb < 2; bb++) {
        int b = w + bb * 8;
        const float4* e4 = (const float4*)(emb2 + b * EMB2);

        float4 e[6];
#pragma unroll
        for (int i = 0; i < 6; i++) e[i] = __ldg(&e4[i * 32 + lane]);

        float v[4];                // {K j0, K j1, V j0, V j1}
#pragma unroll
        for (int t = 0; t < 4; t++) {
            float a = 0.f;
#pragma unroll
            for (int i = 0; i < 6; i++) {
                float4 q = ws[t * 192 + i * 32 + lane];
                a = fmaf(e[i].x, q.x, a); a = fmaf(e[i].y, q.y, a);
                a = fmaf(e[i].z, q.z, a); a = fmaf(e[i].w, q.w, a);
            }
            v[t] = a;
        }

#pragma unroll
        for (int s = 0; s < 2; s++) {
            int o = 1 << s;
            int bit = (lane >> s) & 1;
#pragma unroll
            for (int j = 0; j < (2 >> s); j++) {
                float keep = bit ? v[2 * j + 1] : v[2 * j];
                float send = bit ? v[2 * j] : v[2 * j + 1];
                v[j] = keep + __shfl_xor_sync(0xffffffffu, send, o);
            }
        }
        v[0] += __shfl_xor_sync(0xffffffffu, v[0], 4);
        v[0] += __shfl_xor_sync(0xffffffffu, v[0], 8);
        v[0] += __shfl_xor_sync(0xffffffffu, v[0], 16);

        if (lane < 2)
            g_K[b * HDIM + j0 + lane] = v[0] + bk[j0 + lane];
        else if (lane < 4)
            g_V[b * HDIM + j0 + lane - 2] = v[0] + bv[j0 + lane - 2];
    }
}

// ---------------------------------------------------------------------------
// Kernel 2 (dedup'd): grid (8 ec, 16 h) = 128 blocks x 256 thr. Each (ec,h)
// Wq chunk (32 KB) staged ONCE (was 4x -> 16 MB traffic, now 4 MB). Thread
// halves give 2-way batch parallelism; 8 bg iterations cover all 16 batches.
// c fold on the ec==0 blocks.
// ---------------------------------------------------------------------------
__global__ __launch_bounds__(256, 2) void weff_kernel(const float* __restrict__ Wq,
                                                      const float* __restrict__ bq) {
    __shared__ float Wq_s[DH * 128];   // 32 KB
    __shared__ float Ks[2 * DH];
    int ec = blockIdx.x;               // 0..7
    int h = blockIdx.y;                // 0..15
    int e0 = ec * 128;
    int tid = threadIdx.x;
    int half = tid >> 7;               // batch sub-index (0/1)
    int ut = tid & 127;                // e within chunk

    if (ec == 0 && tid < B) {
        float a = 0.f;
#pragma unroll 16
        for (int d = 0; d < DH; d++)
            a = fmaf(bq[h * DH + d], g_K[tid * HDIM + h * DH + d], a);
        g_c[tid * NHEAD + h] = a;
    }

    // Stage Wq[h, 0..63, e0..e0+128): 8192 floats, 32 per thread.
    for (int t = tid; t < DH * 128; t += 256) {
        int d = t >> 7, el = t & 127;
        Wq_s[d * 128 + el] = __ldg(&Wq[(h * DH + d) * EMB1 + e0 + el]);
    }

#pragma unroll
    for (int bg = 0; bg < 8; bg++) {
        __syncthreads();
        if (tid < 2 * DH)
            Ks[tid] = g_K[(bg * 2 + (tid >> 6)) * HDIM + h * DH + (tid & 63)];
        __syncthreads();
        int b = bg * 2 + half;
        float a = 0.f;
#pragma unroll 16
        for (int d = 0; d < DH; d++)
            a = fmaf(Wq_s[d * 128 + ut], Ks[half * DH + d], a);
        g_Weff[(b * NHEAD + h) * EMB1 + e0 + ut] = a;
    }
}

// ---------------------------------------------------------------------------
// Kernel 3 (main): EXACT R15 (best measured) — row pairs at (256,2) with the
// balanced mapping p = gx + 18*warp + 144k (max one heavy warp per block).
// ---------------------------------------------------------------------------
__global__ __launch_bounds__(256, 2) void main_kernel(const float* __restrict__ emb1,
                                                      float* __restrict__ out) {
    extern __shared__ float sm[];
    float* Weff_s = sm;                    // 16384 floats
    float* V_s = sm + NHEAD * EMB1;        // 1024 floats
    float* c_s = V_s + HDIM;               // 16 floats

    int b = blockIdx.y;
    int tid = threadIdx.x;

    {
        const float4* Wg = (const float4*)(g_Weff + (size_t)b * NHEAD * EMB1);
        float4* Ws4 = (float4*)Weff_s;
#pragma unroll
        for (int i = 0; i < NHEAD * EMB1 / 4 / 256; i++)
            Ws4[i * 256 + tid] = Wg[i * 256 + tid];
        const float4* Vg = (const float4*)(g_V + (size_t)b * HDIM);
        if (tid < HDIM / 4) ((float4*)V_s)[tid] = Vg[tid];
        if (tid < NHEAD) c_s[tid] = g_c[b * NHEAD + tid];
    }
    __syncthreads();

    int warp = tid >> 5, lane = tid & 31;
    const ulonglong2* Wsd = (const ulonglong2*)Weff_s;
    const float4* Vs4 = (const float4*)V_s;
    int hi = lane >> 4;
    float c_l = c_s[lane & 15];

    for (int p = blockIdx.x + GRIDX * warp; p < LQ / 2; p += GRIDX * 8) {
        const ulonglong2* x0p = (const ulonglong2*)(emb1 + ((size_t)b * LQ + 2 * p) * EMB1);
        const ulonglong2* x1p = x0p + EMB1 / 4;

        ulonglong2 x0 = __ldg(x0p + lane);
        ulonglong2 x1 = __ldg(x1p + lane);

        unsigned long long acc0[NHEAD], acc1[NHEAD];
#pragma unroll
        for (int h = 0; h < NHEAD; h++) { acc0[h] = 0ull; acc1[h] = 0ull; }

#pragma unroll
        for (int i = 0; i < 8; i++) {
            ulonglong2 x0n, x1n;
            if (i < 7) {                               // prefetch next chunk
                x0n = __ldg(x0p + (i + 1) * 32 + lane);
                x1n = __ldg(x1p + (i + 1) * 32 + lane);
            }
#pragma unroll
            for (int h = 0; h < NHEAD; h++) {
                ulonglong2 w = Wsd[h * 256 + i * 32 + lane];
                fma2(acc0[h], x0.x, w.x);
                fma2(acc0[h], x0.y, w.y);
                fma2(acc1[h], x1.x, w.x);
                fma2(acc1[h], x1.y, w.y);
            }
            if (i < 7) { x0 = x0n; x1 = x1n; }
        }

        float v0[NHEAD], v1[NHEAD];
#pragma unroll
        for (int h = 0; h < NHEAD; h++) {
            v0[h] = unpack_sum(acc0[h]);
            v1[h] = unpack_sum(acc1[h]);
        }
#pragma unroll
        for (int s = 0; s < 4; s++) {
            int o = 1 << s;
            int bit = (lane >> s) & 1;
#pragma unroll
            for (int j = 0; j < (8 >> s); j++) {
                float k0 = bit ? v0[2 * j + 1] : v0[2 * j];
                float s0 = bit ? v0[2 * j] : v0[2 * j + 1];
                v0[j] = k0 + __shfl_xor_sync(0xffffffffu, s0, o);
                float k1 = bit ? v1[2 * j + 1] : v1[2 * j];
                float s1 = bit ? v1[2 * j] : v1[2 * j + 1];
                v1[j] = k1 + __shfl_xor_sync(0xffffffffu, s1, o);
            }
        }
        v0[0] += __shfl_xor_sync(0xffffffffu, v0[0], 16);
        v1[0] += __shfl_xor_sync(0xffffffffu, v1[0], 16);

        float sig0 = __fdividef(1.f, 1.f + __expf(-(v0[0] + c_l)));
        float sig1 = __fdividef(1.f, 1.f + __expf(-(v1[0] + c_l)));

        float4* o0 = (float4*)(out + ((size_t)b * LQ + 2 * p) * EMB1);
        float4* o1 = o0 + EMB1 / 4;
#pragma unroll
        for (int i = 0; i < 8; i++) {
            float s0 = __shfl_sync(0xffffffffu, sig0, 2 * i + hi);
            float s1 = __shfl_sync(0xffffffffu, sig1, 2 * i + hi);
            float4 v = Vs4[i * 32 + lane];
            float4 r0, r1;
            r0.x = s0 * v.x; r0.y = s0 * v.y; r0.z = s0 * v.z; r0.w = s0 * v.w;
            r1.x = s1 * v.x; r1.y = s1 * v.y; r1.z = s1 * v.z; r1.w = s1 * v.w;
            o0[i * 32 + lane] = r0;
            o1[i * 32 + lane] = r1;
        }
    }
}

// ---------------------------------------------------------------------------
extern "C" void kernel_launch(void* const* d_in, const int* in_sizes, int n_in,
                              void* d_out, int out_size) {
    const float* emb1 = (const float*)d_in[0];
    const float* emb2 = (const float*)d_in[1];
    const float* Wq   = (const float*)d_in[2];
    const float* bq   = (const float*)d_in[3];
    const float* Wk   = (const float*)d_in[4];
    const float* bk   = (const float*)d_in[5];
    const float* Wv   = (const float*)d_in[6];
    const float* bv   = (const float*)d_in[7];
    float* out = (float*)d_out;

    kv_kernel<<<HDIM / 2, 256>>>(emb2, Wk, bk, Wv, bv);
    weff_kernel<<<dim3(EMB1 / 128, NHEAD), 256>>>(Wq, bq);

    int smem = (NHEAD * EMB1 + HDIM + NHEAD) * (int)sizeof(float);  // ~69.7 KB
    static bool attr_set = false;
    if (!attr_set) {
        cudaFuncSetAttribute(main_kernel, cudaFuncAttributeMaxDynamicSharedMemorySize, smem);
        attr_set = true;
    }
    main_kernel<<<dim3(GRIDX, B), 256, smem>>>(emb1, out);
}